// round 8
// baseline (speedup 1.0000x reference)
#include <cuda_runtime.h>
#include <cuda_bf16.h>
#include <cstdint>

// custom_loss_57956288692862
// x: [16384,1024] fp32 -> 4096 groups of 4 rows: q=4b+0, a=4b+1, dead=4b+2, c=4b+3
// target: [2,4096] int32
// out fp32[4097]: out[0]=mean loss, out[1+b]=eq flag
//
// Per-thread cp.async rings: thread t async-copies exactly the 48B it will
// consume (its q/a/c float4) into a DEPTH=3 smem ring. Completion is ordered
// per-thread via cp.async.wait_group -> NO barriers/mbarriers/producer thread
// in the loop (R4's serialization bug eliminated). In-flight bytes live in
// smem, not registers: regs ~48 AND ~3x12KB outstanding per CTA at 3-4 CTAs/SM
// -> both occupancy and MLP high simultaneously (the R2..R6 tradeoff broken).
// Cross-warp combine deferred to scratch; mean via last-CTA ticket reduction.

#define NB      4096
#define D       1024
#define THREADS 256
#define GRID    512
#define GPC     8              // groups per CTA (contiguous 128KB span)
#define DEPTH   3
#define SLOT    12288          // q(4KB)+a(4KB)+c(4KB)

__device__ float        g_partials[GRID];
__device__ unsigned int g_count;   // zero-init; last CTA resets every launch

__device__ __forceinline__ void cp16(void* dst_smem, const void* src) {
    uint32_t d = (uint32_t)__cvta_generic_to_shared(dst_smem);
    asm volatile("cp.async.cg.shared.global [%0], [%1], 16;"
                 :: "r"(d), "l"(src) : "memory");
}

__global__ __launch_bounds__(THREADS)
void loss_kernel(const float* __restrict__ x,
                 const int* __restrict__ target,
                 float* __restrict__ out,
                 int out_size) {
    __shared__ __align__(16) unsigned char buf[DEPTH][SLOT];
    __shared__ float scratch[GPC][8][6];    // per-group, per-warp partials
    __shared__ int   s_t0[GPC], s_t1[GPC];

    const int t   = threadIdx.x;
    const int wid = t >> 5;
    const int lid = t & 31;
    const int b0  = blockIdx.x * GPC;

    // Prefetch all 16 target scalars for this CTA (overlapped with streaming)
    if (t < GPC) {
        s_t0[t] = __ldg(target + b0 + t);
        s_t1[t] = __ldg(target + NB + b0 + t);
    }

    const char* base = (const char*)x + (size_t)b0 * 16384;   // 4 rows * 4KB
    const int   toff = t * 16;                                 // this thread's float4

    // Prologue: issue DEPTH stages (36KB in flight immediately)
    #pragma unroll
    for (int k = 0; k < DEPTH; k++) {
        const char* src = base + (size_t)k * 16384;
        cp16(&buf[k][toff],        src + toff);            // q row (4b+0)
        cp16(&buf[k][4096 + toff], src + 4096  + toff);    // a row (4b+1)
        cp16(&buf[k][8192 + toff], src + 12288 + toff);    // c row (4b+3)
        asm volatile("cp.async.commit_group;" ::: "memory");
    }

    for (int k = 0; k < GPC; k++) {
        const int s = k % DEPTH;
        // Allow DEPTH-1 groups outstanding -> oldest (stage k) complete
        asm volatile("cp.async.wait_group %0;" :: "n"(DEPTH - 1) : "memory");

        const float4 q4 = *reinterpret_cast<const float4*>(&buf[s][toff]);
        const float4 a4 = *reinterpret_cast<const float4*>(&buf[s][4096 + toff]);
        const float4 c4 = *reinterpret_cast<const float4*>(&buf[s][8192 + toff]);

        // Refill slot s with stage k+DEPTH (writes land >>later than our LDS)
        if (k + DEPTH < GPC) {
            const char* src = base + (size_t)(k + DEPTH) * 16384;
            cp16(&buf[s][toff],        src + toff);
            cp16(&buf[s][4096 + toff], src + 4096  + toff);
            cp16(&buf[s][8192 + toff], src + 12288 + toff);
        }
        asm volatile("cp.async.commit_group;" ::: "memory");  // keep group count aligned

        float nq = q4.x*q4.x + q4.y*q4.y + q4.z*q4.z + q4.w*q4.w;
        float na = a4.x*a4.x + a4.y*a4.y + a4.z*a4.z + a4.w*a4.w;
        float nc = c4.x*c4.x + c4.y*c4.y + c4.z*c4.z + c4.w*c4.w;
        float qa = q4.x*a4.x + q4.y*a4.y + q4.z*a4.z + q4.w*a4.w;
        float ac = a4.x*c4.x + a4.y*c4.y + a4.z*c4.z + a4.w*c4.w;
        float qc = q4.x*c4.x + q4.y*c4.y + q4.z*c4.z + q4.w*c4.w;

        // Warp butterfly; shuffles overlap the in-flight cp.async stages
        #pragma unroll
        for (int off = 16; off > 0; off >>= 1) {
            nq += __shfl_xor_sync(0xFFFFFFFFu, nq, off);
            na += __shfl_xor_sync(0xFFFFFFFFu, na, off);
            nc += __shfl_xor_sync(0xFFFFFFFFu, nc, off);
            qa += __shfl_xor_sync(0xFFFFFFFFu, qa, off);
            ac += __shfl_xor_sync(0xFFFFFFFFu, ac, off);
            qc += __shfl_xor_sync(0xFFFFFFFFu, qc, off);
        }
        if (lid == 0) {
            scratch[k][wid][0] = nq; scratch[k][wid][1] = na;
            scratch[k][wid][2] = nc; scratch[k][wid][3] = qa;
            scratch[k][wid][4] = ac; scratch[k][wid][5] = qc;
        }
    }
    __syncthreads();   // all warps' scratch visible

    // Finalize: one group per thread (threads 0..7, all in warp 0)
    float locLoss = 0.0f;
    if (t < GPC) {
        float snq = 0.f, sna = 0.f, snc = 0.f, sqa = 0.f, sac = 0.f, sqc = 0.f;
        #pragma unroll
        for (int w = 0; w < 8; w++) {
            snq += scratch[t][w][0]; sna += scratch[t][w][1];
            snc += scratch[t][w][2]; sqa += scratch[t][w][3];
            sac += scratch[t][w][4]; sqc += scratch[t][w][5];
        }
        const int b = b0 + t;

        float iq = 1.0f / fmaxf(sqrtf(snq), 1e-12f);
        float ia = 1.0f / fmaxf(sqrtf(sna), 1e-12f);
        float ic = 1.0f / fmaxf(sqrtf(snc), 1e-12f);

        float dqa = sqa * iq * ia;
        float dac = sac * ia * ic;
        float dqc = sqc * iq * ic;

        float t0 = (float)s_t0[t];
        float t1 = (float)s_t1[t];

        float eqa = __expf(dqa);
        float eac = __expf(dac);
        float eqc = __expf(dqc);

        float up   = fmaxf((1.0f - t0) * eqa + (1.0f - t1) * eqc, 1e-8f);
        float down = fmaxf(t0 * eqa + t1 * eqc, 1e-8f);

        locLoss = __logf(up + eac) - __logf(down);

        int correct = (dqa > dqc) ? 1 : 0;
        float eq = (correct == s_t0[t]) ? 1.0f : 0.0f;
        if (1 + b < out_size) out[1 + b] = eq;
    }

    // Warp 0 holds all GPC losses -> one partial per CTA
    __shared__ bool s_last;
    if (wid == 0) {
        #pragma unroll
        for (int off = 16; off > 0; off >>= 1)
            locLoss += __shfl_xor_sync(0xFFFFFFFFu, locLoss, off);
        if (lid == 0) {
            g_partials[blockIdx.x] = locLoss;
            __threadfence();
            unsigned int ticket = atomicAdd(&g_count, 1u);
            s_last = (ticket == GRID - 1);
        }
    }
    __syncthreads();

    if (s_last) {
        __threadfence();   // acquire: see all partials
        float sum = 0.f;
        #pragma unroll
        for (int i = 0; i < GRID / THREADS; i++)    // 2 per thread
            sum += g_partials[t + i * THREADS];

        #pragma unroll
        for (int off = 16; off > 0; off >>= 1)
            sum += __shfl_xor_sync(0xFFFFFFFFu, sum, off);
        __shared__ float s_red[8];
        if (lid == 0) s_red[wid] = sum;
        __syncthreads();
        if (t == 0) {
            float total = 0.f;
            #pragma unroll
            for (int w = 0; w < 8; w++) total += s_red[w];
            out[0] = total * (1.0f / (float)NB);
            g_count = 0;   // reset for next graph replay
        }
    }
}

extern "C" void kernel_launch(void* const* d_in, const int* in_sizes, int n_in,
                              void* d_out, int out_size) {
    const float* x      = (const float*)d_in[0];
    const int*   target = (const int*)d_in[1];
    float*       out    = (float*)d_out;

    loss_kernel<<<GRID, THREADS>>>(x, target, out, out_size);
}

// round 9
// speedup vs baseline: 1.0098x; 1.0098x over previous
#include <cuda_runtime.h>
#include <cuda_bf16.h>
#include <cstdint>

// custom_loss_57956288692862
// x: [16384,1024] fp32 -> 4096 groups of 4 rows: q=4b+0, a=4b+1, dead=4b+2, c=4b+3
// target: [2,4096] int32
// out fp32[4097]: out[0]=mean loss, out[1+b]=eq flag
//
// Per-thread cp.async rings: thread t async-copies exactly the 48B it will
// consume (its q/a/c float4) into a DEPTH=3 smem ring. Completion is ordered
// per-thread via cp.async.wait_group -> NO barriers/mbarriers/producer thread
// in the loop (R4's serialization bug eliminated). In-flight bytes live in
// smem, not registers: regs ~48 AND ~3x12KB outstanding per CTA at 3-4 CTAs/SM
// -> both occupancy and MLP high simultaneously (the R2..R6 tradeoff broken).
// Cross-warp combine deferred to scratch; mean via last-CTA ticket reduction.

#define NB      4096
#define D       1024
#define THREADS 256
#define GRID    512
#define GPC     8              // groups per CTA (contiguous 128KB span)
#define DEPTH   3
#define SLOT    12288          // q(4KB)+a(4KB)+c(4KB)

__device__ float        g_partials[GRID];
__device__ unsigned int g_count;   // zero-init; last CTA resets every launch

__device__ __forceinline__ void cp16(void* dst_smem, const void* src) {
    uint32_t d = (uint32_t)__cvta_generic_to_shared(dst_smem);
    asm volatile("cp.async.cg.shared.global [%0], [%1], 16;"
                 :: "r"(d), "l"(src) : "memory");
}

__global__ __launch_bounds__(THREADS)
void loss_kernel(const float* __restrict__ x,
                 const int* __restrict__ target,
                 float* __restrict__ out,
                 int out_size) {
    __shared__ __align__(16) unsigned char buf[DEPTH][SLOT];
    __shared__ float scratch[GPC][8][6];    // per-group, per-warp partials
    __shared__ int   s_t0[GPC], s_t1[GPC];

    const int t   = threadIdx.x;
    const int wid = t >> 5;
    const int lid = t & 31;
    const int b0  = blockIdx.x * GPC;

    // Prefetch all 16 target scalars for this CTA (overlapped with streaming)
    if (t < GPC) {
        s_t0[t] = __ldg(target + b0 + t);
        s_t1[t] = __ldg(target + NB + b0 + t);
    }

    const char* base = (const char*)x + (size_t)b0 * 16384;   // 4 rows * 4KB
    const int   toff = t * 16;                                 // this thread's float4

    // Prologue: issue DEPTH stages (36KB in flight immediately)
    #pragma unroll
    for (int k = 0; k < DEPTH; k++) {
        const char* src = base + (size_t)k * 16384;
        cp16(&buf[k][toff],        src + toff);            // q row (4b+0)
        cp16(&buf[k][4096 + toff], src + 4096  + toff);    // a row (4b+1)
        cp16(&buf[k][8192 + toff], src + 12288 + toff);    // c row (4b+3)
        asm volatile("cp.async.commit_group;" ::: "memory");
    }

    for (int k = 0; k < GPC; k++) {
        const int s = k % DEPTH;
        // Allow DEPTH-1 groups outstanding -> oldest (stage k) complete
        asm volatile("cp.async.wait_group %0;" :: "n"(DEPTH - 1) : "memory");

        const float4 q4 = *reinterpret_cast<const float4*>(&buf[s][toff]);
        const float4 a4 = *reinterpret_cast<const float4*>(&buf[s][4096 + toff]);
        const float4 c4 = *reinterpret_cast<const float4*>(&buf[s][8192 + toff]);

        // Refill slot s with stage k+DEPTH (writes land >>later than our LDS)
        if (k + DEPTH < GPC) {
            const char* src = base + (size_t)(k + DEPTH) * 16384;
            cp16(&buf[s][toff],        src + toff);
            cp16(&buf[s][4096 + toff], src + 4096  + toff);
            cp16(&buf[s][8192 + toff], src + 12288 + toff);
        }
        asm volatile("cp.async.commit_group;" ::: "memory");  // keep group count aligned

        float nq = q4.x*q4.x + q4.y*q4.y + q4.z*q4.z + q4.w*q4.w;
        float na = a4.x*a4.x + a4.y*a4.y + a4.z*a4.z + a4.w*a4.w;
        float nc = c4.x*c4.x + c4.y*c4.y + c4.z*c4.z + c4.w*c4.w;
        float qa = q4.x*a4.x + q4.y*a4.y + q4.z*a4.z + q4.w*a4.w;
        float ac = a4.x*c4.x + a4.y*c4.y + a4.z*c4.z + a4.w*c4.w;
        float qc = q4.x*c4.x + q4.y*c4.y + q4.z*c4.z + q4.w*c4.w;

        // Warp butterfly; shuffles overlap the in-flight cp.async stages
        #pragma unroll
        for (int off = 16; off > 0; off >>= 1) {
            nq += __shfl_xor_sync(0xFFFFFFFFu, nq, off);
            na += __shfl_xor_sync(0xFFFFFFFFu, na, off);
            nc += __shfl_xor_sync(0xFFFFFFFFu, nc, off);
            qa += __shfl_xor_sync(0xFFFFFFFFu, qa, off);
            ac += __shfl_xor_sync(0xFFFFFFFFu, ac, off);
            qc += __shfl_xor_sync(0xFFFFFFFFu, qc, off);
        }
        if (lid == 0) {
            scratch[k][wid][0] = nq; scratch[k][wid][1] = na;
            scratch[k][wid][2] = nc; scratch[k][wid][3] = qa;
            scratch[k][wid][4] = ac; scratch[k][wid][5] = qc;
        }
    }
    __syncthreads();   // all warps' scratch visible

    // Finalize: one group per thread (threads 0..7, all in warp 0)
    float locLoss = 0.0f;
    if (t < GPC) {
        float snq = 0.f, sna = 0.f, snc = 0.f, sqa = 0.f, sac = 0.f, sqc = 0.f;
        #pragma unroll
        for (int w = 0; w < 8; w++) {
            snq += scratch[t][w][0]; sna += scratch[t][w][1];
            snc += scratch[t][w][2]; sqa += scratch[t][w][3];
            sac += scratch[t][w][4]; sqc += scratch[t][w][5];
        }
        const int b = b0 + t;

        float iq = 1.0f / fmaxf(sqrtf(snq), 1e-12f);
        float ia = 1.0f / fmaxf(sqrtf(sna), 1e-12f);
        float ic = 1.0f / fmaxf(sqrtf(snc), 1e-12f);

        float dqa = sqa * iq * ia;
        float dac = sac * ia * ic;
        float dqc = sqc * iq * ic;

        float t0 = (float)s_t0[t];
        float t1 = (float)s_t1[t];

        float eqa = __expf(dqa);
        float eac = __expf(dac);
        float eqc = __expf(dqc);

        float up   = fmaxf((1.0f - t0) * eqa + (1.0f - t1) * eqc, 1e-8f);
        float down = fmaxf(t0 * eqa + t1 * eqc, 1e-8f);

        locLoss = __logf(up + eac) - __logf(down);

        int correct = (dqa > dqc) ? 1 : 0;
        float eq = (correct == s_t0[t]) ? 1.0f : 0.0f;
        if (1 + b < out_size) out[1 + b] = eq;
    }

    // Warp 0 holds all GPC losses -> one partial per CTA
    __shared__ bool s_last;
    if (wid == 0) {
        #pragma unroll
        for (int off = 16; off > 0; off >>= 1)
            locLoss += __shfl_xor_sync(0xFFFFFFFFu, locLoss, off);
        if (lid == 0) {
            g_partials[blockIdx.x] = locLoss;
            __threadfence();
            unsigned int ticket = atomicAdd(&g_count, 1u);
            s_last = (ticket == GRID - 1);
        }
    }
    __syncthreads();

    if (s_last) {
        __threadfence();   // acquire: see all partials
        float sum = 0.f;
        #pragma unroll
        for (int i = 0; i < GRID / THREADS; i++)    // 2 per thread
            sum += g_partials[t + i * THREADS];

        #pragma unroll
        for (int off = 16; off > 0; off >>= 1)
            sum += __shfl_xor_sync(0xFFFFFFFFu, sum, off);
        __shared__ float s_red[8];
        if (lid == 0) s_red[wid] = sum;
        __syncthreads();
        if (t == 0) {
            float total = 0.f;
            #pragma unroll
            for (int w = 0; w < 8; w++) total += s_red[w];
            out[0] = total * (1.0f / (float)NB);
            g_count = 0;   // reset for next graph replay
        }
    }
}

extern "C" void kernel_launch(void* const* d_in, const int* in_sizes, int n_in,
                              void* d_out, int out_size) {
    const float* x      = (const float*)d_in[0];
    const int*   target = (const int*)d_in[1];
    float*       out    = (float*)d_out;

    loss_kernel<<<GRID, THREADS>>>(x, target, out, out_size);
}